// round 10
// baseline (speedup 1.0000x reference)
#include <cuda_runtime.h>
#include <cuda_fp16.h>
#include <cstdint>

// Problem constants
#define NB   64            // batch
#define CC   128           // channels
#define TT   300           // time
#define VV   25            // vertices
#define KK   3             // adjacency count
#define TV   (TT*VV)       // 7500
#define CO   (CC*KK)       // 384 output channels of 1x1 conv
#define NELEM (NB*CC*TT*VV) // 61,440,000 output elems
#define BN_EPS 1e-5f
#define RPAD 7552          // padded row count per n for g_xh
#define KP 136             // padded k-dim of fp16 smem tiles
#define R5 125             // real rows per fused block (5 t * 25 v)
#define Y1S 132            // y1s row stride (floats)
#define OS 130             // out_s per-channel stride (5 t * 26 + pad)
#define TBLKS (TT/5)       // 60
#define NBLK2 (TBLKS*NB)   // 3840

typedef unsigned long long u64;

// ---------------- packed f32x2 helpers --------------------------------------
__device__ __forceinline__ u64 ffma2(u64 a, u64 b, u64 c) {
    u64 d;
    asm("fma.rn.f32x2 %0, %1, %2, %3;" : "=l"(d) : "l"(a), "l"(b), "l"(c));
    return d;
}
__device__ __forceinline__ u64 pack2(float lo, float hi) {
    u64 d;
    asm("mov.b64 %0, {%1, %2};" : "=l"(d) : "f"(lo), "f"(hi));
    return d;
}

// ---------------- fp16 mma.sync (base PTX, works on plain sm_103) -----------
__device__ __forceinline__ void mma16816(float* c, const uint32_t* a, const uint32_t* b) {
    asm volatile(
        "mma.sync.aligned.m16n8k16.row.col.f32.f16.f16.f32 "
        "{%0,%1,%2,%3}, {%4,%5,%6,%7}, {%8,%9}, {%0,%1,%2,%3};"
        : "+f"(c[0]), "+f"(c[1]), "+f"(c[2]), "+f"(c[3])
        : "r"(a[0]), "r"(a[1]), "r"(a[2]), "r"(a[3]), "r"(b[0]), "r"(b[1]));
}

// ---------------- scratch ----------------------------------------------------
__device__ __half g_xh[(size_t)NB * RPAD * CC];     // x transposed, fp16 [n][r][c]
__device__ __half g_Wh[CO * CC];                    // W fp16 ([o][c], k-contig)
__device__ float g_bias2[CC * VV];                  // bias folded through A
__device__ float g_psum[NBLK2 * CC];
__device__ float g_psq[NBLK2 * CC];
__device__ float g_scale[CC];
__device__ float g_shift[CC];

// ---------------- kernel 0: prep (W -> fp16, fold bias through A) -----------
__global__ void prep_kernel(const float* __restrict__ W,
                            const float* __restrict__ b,
                            const float* __restrict__ A) {
    int tid = blockIdx.x * blockDim.x + threadIdx.x;
    int stride = gridDim.x * blockDim.x;
    for (int i = tid; i < CC * CO; i += stride)
        g_Wh[i] = __float2half(W[i]);
    for (int i = tid; i < CC * VV; i += stride) {
        int c = i / VV, w = i % VV;
        float s = 0.f;
        #pragma unroll
        for (int k = 0; k < KK; k++) {
            float cs = 0.f;
            #pragma unroll
            for (int v = 0; v < VV; v++) cs += A[k * VV * VV + v * VV + w];
            s += b[k * CC + c] * cs;
        }
        g_bias2[i] = s;
    }
}

// ---------------- kernel 1: transpose x [n,c,r] -> fp16 [n,r,c] -------------
__global__ void __launch_bounds__(256) transpose_split_kernel(const float* __restrict__ x) {
    __shared__ float tile[32][129];
    const int r0 = blockIdx.x * 128;
    const int c0 = blockIdx.y * 32;
    const int n  = blockIdx.z;
    const int tid = threadIdx.x;

    #pragma unroll
    for (int j = 0; j < 16; j++) {
        int e = tid + 256 * j;
        int cl = e >> 7, rl = e & 127;
        int rg = r0 + rl;
        float v = 0.f;
        if (rg < TV) v = x[((size_t)n * CC + c0 + cl) * TV + rg];
        tile[cl][rl] = v;
    }
    __syncthreads();
    #pragma unroll
    for (int j = 0; j < 16; j++) {
        int e = tid + 256 * j;
        int rl = e >> 5, cl = e & 31;
        g_xh[((size_t)n * RPAD + r0 + rl) * CC + c0 + cl] = __float2half(tile[cl][rl]);
    }
}

// ---------------- kernel 2: FUSED gemm + aggregation + residual + stats -----
// Per CTA: one n, 5 t (125 rows padded to 128). Three o-passes; o-pass k is
// exactly adjacency k over all 128 channels. After each pass the acc tile goes
// to smem (fp32) and is aggregated over v into out_s[c][(t,w)] immediately.
// Then residual + relu + per-channel stats + coalesced store. y1 never touches
// global memory.
#define SMEM_SA    0
#define SMEM_SB    34816                 // union with y1s
#define SMEM_OUTS  102400
#define SMEM_AS    168960
#define SMEM_FUSED (168960 + 8400)       // 177360 B

__global__ void __launch_bounds__(256) fused_kernel(const float* __restrict__ x,
                                                    const float* __restrict__ A,
                                                    float* __restrict__ out) {
    extern __shared__ char sm[];
    __half* sA   = (__half*)(sm + SMEM_SA);     // [128][KP]
    __half* sB   = (__half*)(sm + SMEM_SB);     // [128][KP]   (union with y1s)
    float* y1s   = (float*)(sm + SMEM_SB);      // [128][Y1S]
    float* out_s = (float*)(sm + SMEM_OUTS);    // [128][OS] = [c][t*26+w]
    float* A_s   = (float*)(sm + SMEM_AS);      // [75][28] w-padded

    const int tblk = blockIdx.x, n = blockIdx.y;
    const int r0 = tblk * R5;
    const int tid = threadIdx.x;
    const int wid = tid >> 5, lane = tid & 31;
    const int wm = wid & 1, wn = wid >> 1;
    const int lr = lane >> 2, kq = (lane & 3) * 2;
    const int cc = tid & 127, th = tid >> 7;

    // A_s: [kv][w] zero-padded to 28
    for (int e = tid; e < KK * VV * 28; e += 256) {
        int kv = e / 28, w = e - kv * 28;
        A_s[e] = (w < VV) ? A[kv * VV + w] : 0.f;
    }
    // out_s init with folded bias (w>=25 or t>=5 pads -> 0)
    for (int e = tid; e < 128 * OS; e += 256) {
        int c = e / OS, q = e - c * OS;
        int t = q / 26, w = q - t * 26;
        out_s[e] = (w < VV && t < 5) ? g_bias2[c * VV + w] : 0.f;
    }
    // sA: 128 rows of x (fp16), rows r0..r0+127 (g_xh zero-padded to RPAD)
    {
        const __half* src = g_xh + ((size_t)n * RPAD + r0) * CC;
        #pragma unroll
        for (int i = 0; i < 8; i++) {
            int q = tid + 256 * i;
            int row = q >> 4, c8 = (q & 15) * 8;
            *(uint4*)(sA + row * KP + c8) = *(const uint4*)(src + row * CC + c8);
        }
    }

    for (int k = 0; k < KK; k++) {
        __syncthreads();    // prev aggregation done with y1s (aliases sB)
        {
            const __half* src = g_Wh + (size_t)(k * 128) * CC;
            #pragma unroll
            for (int i = 0; i < 8; i++) {
                int q = tid + 256 * i;
                int row = q >> 4, c8 = (q & 15) * 8;
                *(uint4*)(sB + row * KP + c8) = *(const uint4*)(src + row * CC + c8);
            }
        }
        __syncthreads();

        float acc[4][4][4];
        #pragma unroll
        for (int mt = 0; mt < 4; mt++)
            #pragma unroll
            for (int nt = 0; nt < 4; nt++)
                #pragma unroll
                for (int j = 0; j < 4; j++) acc[mt][nt][j] = 0.f;

        #pragma unroll
        for (int kk = 0; kk < 8; kk++) {
            const int k0 = kk * 16 + kq;
            uint32_t af[4][4], bf[4][2];
            #pragma unroll
            for (int mt = 0; mt < 4; mt++) {
                int rm = wm * 64 + mt * 16 + lr;
                af[mt][0] = *(const uint32_t*)(sA + rm * KP + k0);
                af[mt][1] = *(const uint32_t*)(sA + (rm + 8) * KP + k0);
                af[mt][2] = *(const uint32_t*)(sA + rm * KP + k0 + 8);
                af[mt][3] = *(const uint32_t*)(sA + (rm + 8) * KP + k0 + 8);
            }
            #pragma unroll
            for (int nt = 0; nt < 4; nt++) {
                int rn = wn * 32 + nt * 8 + lr;
                bf[nt][0] = *(const uint32_t*)(sB + rn * KP + k0);
                bf[nt][1] = *(const uint32_t*)(sB + rn * KP + k0 + 8);
            }
            #pragma unroll
            for (int mt = 0; mt < 4; mt++)
                #pragma unroll
                for (int nt = 0; nt < 4; nt++)
                    mma16816(acc[mt][nt], af[mt], bf[nt]);
        }
        __syncthreads();    // all warps done reading sB before y1s overwrite

        #pragma unroll
        for (int mt = 0; mt < 4; mt++) {
            int row = wm * 64 + mt * 16 + lr;
            #pragma unroll
            for (int nt = 0; nt < 4; nt++) {
                int col = wn * 32 + nt * 8 + kq;
                *(float2*)(y1s + row * Y1S + col) =
                    make_float2(acc[mt][nt][0], acc[mt][nt][1]);
                *(float2*)(y1s + (row + 8) * Y1S + col) =
                    make_float2(acc[mt][nt][2], acc[mt][nt][3]);
            }
        }
        __syncthreads();

        // aggregation over v for this k: out_s[c][t*26+w] += sum_v y1*A
        for (int t = th; t < 5; t += 2) {
            float yv[VV];
            #pragma unroll
            for (int v = 0; v < VV; v++)
                yv[v] = y1s[(t * VV + v) * Y1S + cc];
            float* orow = out_s + cc * OS + t * 26;
            u64 racc[13];
            #pragma unroll
            for (int j = 0; j < 13; j++) racc[j] = *(u64*)(orow + 2 * j);
            #pragma unroll
            for (int v = 0; v < VV; v++) {
                u64 y2 = pack2(yv[v], yv[v]);
                const u64* Ar = (const u64*)(A_s + (k * VV + v) * 28);
                #pragma unroll
                for (int j = 0; j < 13; j++)
                    racc[j] = ffma2(y2, Ar[j], racc[j]);
            }
            #pragma unroll
            for (int j = 0; j < 13; j++) *(u64*)(orow + 2 * j) = racc[j];
        }
    }
    __syncthreads();

    // Phase A: coalesced residual + relu (in smem)
    const size_t gbase = ((size_t)n * CC) * TV + r0;
    for (int e = tid; e < 128 * R5; e += 256) {
        int c = e / R5, r = e - c * R5;
        int t = r / VV, w = r - t * VV;
        float* p = out_s + c * OS + t * 26 + w;
        *p = fmaxf(*p + x[gbase + (size_t)c * TV + r], 0.f);
    }
    __syncthreads();

    // Phase B: per-channel stats partials
    float bs = 0.f, bq = 0.f;
    {
        int rbeg = th ? 63 : 0, rend = th ? R5 : 63;
        for (int r = rbeg; r < rend; r++) {
            int t = r / VV, w = r - t * VV;
            float v = out_s[cc * OS + t * 26 + w];
            bs += v; bq += v * v;
        }
    }
    float* scr = A_s;   // A_s dead; reuse 512 floats
    scr[tid] = bs; scr[256 + tid] = bq;

    // Phase C: coalesced store to out
    for (int e = tid; e < 128 * R5; e += 256) {
        int c = e / R5, r = e - c * R5;
        int t = r / VV, w = r - t * VV;
        out[gbase + (size_t)c * TV + r] = out_s[c * OS + t * 26 + w];
    }
    __syncthreads();
    if (th == 0) {
        int p = (n * TBLKS + tblk) * CC + cc;
        g_psum[p] = scr[cc] + scr[cc + 128];
        g_psq[p]  = scr[256 + cc] + scr[256 + cc + 128];
    }
}

// ---------------- kernel 3: reduce partials, fold BN into scale/shift ------
__global__ void __launch_bounds__(256) stats_kernel(const float* __restrict__ gamma,
                                                    const float* __restrict__ beta) {
    const int c = blockIdx.x;
    const int tid = threadIdx.x;
    __shared__ float s1[256], s2[256];
    float a = 0.f, b2 = 0.f;
    for (int i = tid; i < NBLK2; i += 256) {
        a += g_psum[i * CC + c];
        b2 += g_psq[i * CC + c];
    }
    s1[tid] = a; s2[tid] = b2;
    __syncthreads();
    for (int s = 128; s > 0; s >>= 1) {
        if (tid < s) { s1[tid] += s1[tid + s]; s2[tid] += s2[tid + s]; }
        __syncthreads();
    }
    if (tid == 0) {
        const float inv = 1.f / (float)(NB * TT * VV);
        float mean = s1[0] * inv;
        float var = s2[0] * inv - mean * mean;
        float sc = gamma[c] * rsqrtf(var + BN_EPS);
        g_scale[c] = sc;
        g_shift[c] = beta[c] - mean * sc;
    }
}

// ---------------- kernel 4: in-place normalize + A passthrough tail --------
__global__ void normalize_kernel(float* __restrict__ out,
                                 const float* __restrict__ A,
                                 int out_size) {
    const int total4 = NELEM / 4;
    int stride = gridDim.x * blockDim.x;
    for (int idx = blockIdx.x * blockDim.x + threadIdx.x; idx < total4; idx += stride) {
        int e = idx * 4;
        int c = (e / TV) % CC;
        float sc = g_scale[c], sh = g_shift[c];
        float4 v = ((float4*)out)[idx];
        v.x = fmaf(v.x, sc, sh);
        v.y = fmaf(v.y, sc, sh);
        v.z = fmaf(v.z, sc, sh);
        v.w = fmaf(v.w, sc, sh);
        ((float4*)out)[idx] = v;
    }
    if (out_size > NELEM) {
        for (int j = blockIdx.x * blockDim.x + threadIdx.x;
             j < out_size - NELEM && j < KK * VV * VV; j += stride)
            out[NELEM + j] = A[j];
    }
}

// ---------------- launch ----------------------------------------------------
extern "C" void kernel_launch(void* const* d_in, const int* in_sizes, int n_in,
                              void* d_out, int out_size) {
    const float* x     = (const float*)d_in[0];
    const float* A     = (const float*)d_in[1];
    const float* W     = (const float*)d_in[2];
    const float* b     = (const float*)d_in[3];
    const float* gamma = (const float*)d_in[4];
    const float* beta  = (const float*)d_in[5];
    float* out = (float*)d_out;

    cudaFuncSetAttribute(fused_kernel,
                         cudaFuncAttributeMaxDynamicSharedMemorySize, SMEM_FUSED);

    prep_kernel<<<64, 256>>>(W, b, A);

    dim3 gt(RPAD / 128, CC / 32, NB);          // (59, 4, 64)
    transpose_split_kernel<<<gt, 256>>>(x);

    dim3 gf(TBLKS, NB);                        // (60, 64)
    fused_kernel<<<gf, 256, SMEM_FUSED>>>(x, A, out);

    stats_kernel<<<CC, 256>>>(gamma, beta);

    normalize_kernel<<<2048, 256>>>(out, A, out_size);
}

// round 11
// speedup vs baseline: 1.5240x; 1.5240x over previous
#include <cuda_runtime.h>
#include <cuda_fp16.h>
#include <cstdint>

// Problem constants
#define NB   64            // batch
#define CC   128           // channels
#define TT   300           // time
#define VV   25            // vertices
#define KK   3             // adjacency count
#define TV   (TT*VV)       // 7500 rows per n (r = t*25+w)
#define KD   (KK*CC)       // 384 = main GEMM K-dim
#define NELEM (NB*CC*TT*VV) // 61,440,000 output elems
#define BN_EPS 1e-5f
#define RPAD 7552          // padded rows per n for g_z (59*128)
#define KP 136             // padded k-dim of mgemm smem tiles (fp16)
#define XS 40              // zgemm sX row stride (fp16)
#define SS 136             // zgemm stage row stride (fp16)
#define MBLK 59            // mgemm row-blocks per n
#define NBLK2 (MBLK*NB)    // 3776 stats partials

typedef unsigned long long u64;

// ---------------- fp16 mma.sync (base PTX, works on plain sm_103) -----------
__device__ __forceinline__ void mma16816(float* c, const uint32_t* a, const uint32_t* b) {
    asm volatile(
        "mma.sync.aligned.m16n8k16.row.col.f32.f16.f16.f32 "
        "{%0,%1,%2,%3}, {%4,%5,%6,%7}, {%8,%9}, {%0,%1,%2,%3};"
        : "+f"(c[0]), "+f"(c[1]), "+f"(c[2]), "+f"(c[3])
        : "r"(a[0]), "r"(a[1]), "r"(a[2]), "r"(a[3]), "r"(b[0]), "r"(b[1]));
}

// ---------------- scratch ----------------------------------------------------
__device__ __half g_z[(size_t)NB * RPAD * KD];   // z[n][r][(k,ci)] fp16 (~371MB)
__device__ __half g_W2[CC * KD];                 // W2[c][(k,ci)] fp16
__device__ float g_bias2[CC * VV];               // bias folded through A
__device__ float g_psum[NBLK2 * CC];
__device__ float g_psq[NBLK2 * CC];
__device__ float g_scale[CC];
__device__ float g_shift[CC];

// ---------------- kernel 0: prep (W2 fp16 permuted, fold bias) --------------
__global__ void prep_kernel(const float* __restrict__ W,
                            const float* __restrict__ b,
                            const float* __restrict__ A) {
    int tid = blockIdx.x * blockDim.x + threadIdx.x;
    int stride = gridDim.x * blockDim.x;
    // W2[c][k*128+ci] = W[(k*128+c)][ci]
    for (int i = tid; i < CC * KD; i += stride) {
        int c = i / KD, rem = i - c * KD;
        int k = rem >> 7, ci = rem & 127;
        g_W2[i] = __float2half(W[(k * CC + c) * CC + ci]);
    }
    // bias2[c][w] = sum_k b[k*CC+c] * sum_v A[k,v,w]
    for (int i = tid; i < CC * VV; i += stride) {
        int c = i / VV, w = i % VV;
        float s = 0.f;
        #pragma unroll
        for (int k = 0; k < KK; k++) {
            float cs = 0.f;
            #pragma unroll
            for (int v = 0; v < VV; v++) cs += A[k * VV * VV + v * VV + w];
            s += b[k * CC + c] * cs;
        }
        g_bias2[i] = s;
    }
}

// ---------------- kernel 1: z-GEMM  z[n][t*25+w][k*128+ci] -------------------
// Per CTA: one n, 10 t. Per t: D[ci=128][(k,w)=75pad96] = X[ci][v<=25pad32] *
// BA[(k,w)][v], via m16n8k16. 8 warps: wm=wid&3 (32 m-rows), wn=wid>>2 (48 n).
__global__ void __launch_bounds__(256) zgemm_kernel(const float* __restrict__ x,
                                                    const float* __restrict__ A) {
    __shared__ __half sX[128 * XS];       // [ci][v] padded
    __shared__ __half sBA[96 * XS];       // [(k*25+w)][v] padded, A transposed
    __shared__ __half stage[96 * SS];     // [(k,w)][ci]

    const int tb = blockIdx.x, n = blockIdx.y;
    const int tid = threadIdx.x;
    const int wid = tid >> 5, lane = tid & 31;
    const int wm = wid & 3, wn = wid >> 2;
    const int lr = lane >> 2, kq = (lane & 3) * 2;

    // zero pads once, then fill BA
    for (int e = tid; e < 128 * XS; e += 256) sX[e] = __float2half(0.f);
    for (int e = tid; e < 96 * XS; e += 256) sBA[e] = __float2half(0.f);
    __syncthreads();
    for (int e = tid; e < KK * VV * VV; e += 256) {
        int k = e / (VV * VV), rem = e - k * VV * VV;
        int v = rem / VV, w = rem - v * VV;
        sBA[(k * VV + w) * XS + v] = __float2half(A[e]);
    }
    __syncthreads();

    for (int tt = 0; tt < 10; tt++) {
        const int t = tb * 10 + tt;
        // fill sX[ci][v] from x[n][ci][t*25+v]
        const float* xn = x + (size_t)(n * CC) * TV + t * VV;
        for (int e = tid; e < CC * VV; e += 256) {
            int ci = e / VV, v = e - ci * VV;
            sX[ci * XS + v] = __float2half(xn[(size_t)ci * TV + v]);
        }
        __syncthreads();

        float acc[2][6][4];
        #pragma unroll
        for (int mt = 0; mt < 2; mt++)
            #pragma unroll
            for (int nt = 0; nt < 6; nt++)
                #pragma unroll
                for (int j = 0; j < 4; j++) acc[mt][nt][j] = 0.f;

        #pragma unroll
        for (int kk = 0; kk < 2; kk++) {
            const int k0 = kk * 16 + kq;
            uint32_t af[2][4], bf[6][2];
            #pragma unroll
            for (int mt = 0; mt < 2; mt++) {
                int rm = wm * 32 + mt * 16 + lr;
                af[mt][0] = *(const uint32_t*)(sX + rm * XS + k0);
                af[mt][1] = *(const uint32_t*)(sX + (rm + 8) * XS + k0);
                af[mt][2] = *(const uint32_t*)(sX + rm * XS + k0 + 8);
                af[mt][3] = *(const uint32_t*)(sX + (rm + 8) * XS + k0 + 8);
            }
            #pragma unroll
            for (int nt = 0; nt < 6; nt++) {
                int rn = wn * 48 + nt * 8 + lr;
                bf[nt][0] = *(const uint32_t*)(sBA + rn * XS + k0);
                bf[nt][1] = *(const uint32_t*)(sBA + rn * XS + k0 + 8);
            }
            #pragma unroll
            for (int mt = 0; mt < 2; mt++)
                #pragma unroll
                for (int nt = 0; nt < 6; nt++)
                    mma16816(acc[mt][nt], af[mt], bf[nt]);
        }

        // stage[(k,w)][ci] = D (fp16)
        #pragma unroll
        for (int mt = 0; mt < 2; mt++) {
            int row = wm * 32 + mt * 16 + lr;
            #pragma unroll
            for (int nt = 0; nt < 6; nt++) {
                int col = wn * 48 + nt * 8 + kq;
                stage[col * SS + row]           = __float2half(acc[mt][nt][0]);
                stage[(col + 1) * SS + row]     = __float2half(acc[mt][nt][1]);
                stage[col * SS + row + 8]       = __float2half(acc[mt][nt][2]);
                stage[(col + 1) * SS + row + 8] = __float2half(acc[mt][nt][3]);
            }
        }
        __syncthreads();

        // copy stage rows q=(k*25+w), q<75 -> z[n][t*25+w][k*128 + ci]
        __half* zb = g_z + ((size_t)n * RPAD + t * VV) * KD;
        for (int e = tid; e < 75 * 16; e += 256) {
            int q = e >> 4, h8 = (e & 15);
            int k = q / VV, w = q - k * VV;
            *(uint4*)(zb + (size_t)w * KD + k * CC + h8 * 8) =
                *(const uint4*)(stage + q * SS + h8 * 8);
        }
        __syncthreads();   // copy done before next fill/mma cycle
    }
}

// ---------------- kernel 2: main GEMM + bias + residual + relu + stats ------
// out[(n),(r=t*25+w)][c] = sum_{kd<384} z[n][r][kd] * W2[c][kd]
// Per CTA: 128 rows x 128 c. K-loop 3 chunks of 128. Epilogue stages D in
// smem (out_s aliases sA/sB), adds bias+residual, relu, writes out, stats.
#define SMEM_M_TOTAL 69632    // sA(34816)+sB(34816); epilogue out_s(66560)+scr

__global__ void __launch_bounds__(256) mgemm_kernel(const float* __restrict__ x,
                                                    float* __restrict__ out) {
    extern __shared__ char sm[];
    __half* sA = (__half*)sm;                   // [128][KP]
    __half* sB = (__half*)(sm + 34816);         // [128][KP]
    float* out_s = (float*)sm;                  // [128 c][130] epilogue alias
    float* scr = (float*)(sm + 66560);          // 512 floats

    const int r0 = blockIdx.x * 128;
    const int n  = blockIdx.y;
    const int tid = threadIdx.x;
    const int wid = tid >> 5, lane = tid & 31;
    const int wm = wid & 1, wn = wid >> 1;
    const int lr = lane >> 2, kq = (lane & 3) * 2;

    float acc[4][4][4];
    #pragma unroll
    for (int mt = 0; mt < 4; mt++)
        #pragma unroll
        for (int nt = 0; nt < 4; nt++)
            #pragma unroll
            for (int j = 0; j < 4; j++) acc[mt][nt][j] = 0.f;

    for (int ch = 0; ch < 3; ch++) {
        __syncthreads();
        {
            const __half* srcA = g_z + ((size_t)n * RPAD + r0) * KD + ch * CC;
            const __half* srcB = g_W2 + ch * CC;
            #pragma unroll
            for (int i = 0; i < 8; i++) {
                int q = tid + 256 * i;
                int row = q >> 4, c8 = (q & 15) * 8;
                *(uint4*)(sA + row * KP + c8) = *(const uint4*)(srcA + (size_t)row * KD + c8);
                *(uint4*)(sB + row * KP + c8) = *(const uint4*)(srcB + (size_t)row * KD + c8);
            }
        }
        __syncthreads();

        #pragma unroll
        for (int kk = 0; kk < 8; kk++) {
            const int k0 = kk * 16 + kq;
            uint32_t af[4][4], bf[4][2];
            #pragma unroll
            for (int mt = 0; mt < 4; mt++) {
                int rm = wm * 64 + mt * 16 + lr;
                af[mt][0] = *(const uint32_t*)(sA + rm * KP + k0);
                af[mt][1] = *(const uint32_t*)(sA + (rm + 8) * KP + k0);
                af[mt][2] = *(const uint32_t*)(sA + rm * KP + k0 + 8);
                af[mt][3] = *(const uint32_t*)(sA + (rm + 8) * KP + k0 + 8);
            }
            #pragma unroll
            for (int nt = 0; nt < 4; nt++) {
                int rn = wn * 32 + nt * 8 + lr;
                bf[nt][0] = *(const uint32_t*)(sB + rn * KP + k0);
                bf[nt][1] = *(const uint32_t*)(sB + rn * KP + k0 + 8);
            }
            #pragma unroll
            for (int mt = 0; mt < 4; mt++)
                #pragma unroll
                for (int nt = 0; nt < 4; nt++)
                    mma16816(acc[mt][nt], af[mt], bf[nt]);
        }
    }
    __syncthreads();    // done with sA/sB; out_s aliases them

    // stage D: out_s[c][r_loc]
    #pragma unroll
    for (int mt = 0; mt < 4; mt++) {
        int r_loc = wm * 64 + mt * 16 + lr;
        #pragma unroll
        for (int nt = 0; nt < 4; nt++) {
            int cb = wn * 32 + nt * 8 + kq;
            out_s[cb * 130 + r_loc]           = acc[mt][nt][0];
            out_s[(cb + 1) * 130 + r_loc]     = acc[mt][nt][1];
            out_s[cb * 130 + r_loc + 8]       = acc[mt][nt][2];
            out_s[(cb + 1) * 130 + r_loc + 8] = acc[mt][nt][3];
        }
    }
    __syncthreads();

    // Phase A: bias + residual + relu; write out; keep in smem for stats
    for (int e = tid; e < 128 * 128; e += 256) {
        int c = e >> 7, r = e & 127;
        int gr = r0 + r;
        if (gr < TV) {
            size_t gidx = (size_t)(n * CC + c) * TV + gr;
            float v = out_s[c * 130 + r] + g_bias2[c * VV + gr % VV] + x[gidx];
            v = fmaxf(v, 0.f);
            out_s[c * 130 + r] = v;
            out[gidx] = v;
        }
    }
    __syncthreads();

    // Phase B: per-channel stats partials
    const int cc = tid & 127, th = tid >> 7;
    const int rmax = (TV - r0 < 128) ? (TV - r0) : 128;
    float bs = 0.f, bq = 0.f;
    for (int r = th; r < rmax; r += 2) {
        float v = out_s[cc * 130 + r];
        bs += v; bq += v * v;
    }
    scr[tid] = bs; scr[256 + tid] = bq;
    __syncthreads();
    if (th == 0) {
        int p = (n * MBLK + blockIdx.x) * CC + cc;
        g_psum[p] = scr[cc] + scr[cc + 128];
        g_psq[p]  = scr[256 + cc] + scr[256 + cc + 128];
    }
}

// ---------------- kernel 3: reduce partials, fold BN into scale/shift ------
__global__ void __launch_bounds__(256) stats_kernel(const float* __restrict__ gamma,
                                                    const float* __restrict__ beta) {
    const int c = blockIdx.x;
    const int tid = threadIdx.x;
    __shared__ float s1[256], s2[256];
    float a = 0.f, b2 = 0.f;
    for (int i = tid; i < NBLK2; i += 256) {
        a += g_psum[i * CC + c];
        b2 += g_psq[i * CC + c];
    }
    s1[tid] = a; s2[tid] = b2;
    __syncthreads();
    for (int s = 128; s > 0; s >>= 1) {
        if (tid < s) { s1[tid] += s1[tid + s]; s2[tid] += s2[tid + s]; }
        __syncthreads();
    }
    if (tid == 0) {
        const float inv = 1.f / (float)(NB * TT * VV);
        float mean = s1[0] * inv;
        float var = s2[0] * inv - mean * mean;
        float sc = gamma[c] * rsqrtf(var + BN_EPS);
        g_scale[c] = sc;
        g_shift[c] = beta[c] - mean * sc;
    }
}

// ---------------- kernel 4: in-place normalize + A passthrough tail --------
__global__ void normalize_kernel(float* __restrict__ out,
                                 const float* __restrict__ A,
                                 int out_size) {
    const int total4 = NELEM / 4;
    int stride = gridDim.x * blockDim.x;
    for (int idx = blockIdx.x * blockDim.x + threadIdx.x; idx < total4; idx += stride) {
        int e = idx * 4;
        int c = (e / TV) % CC;
        float sc = g_scale[c], sh = g_shift[c];
        float4 v = ((float4*)out)[idx];
        v.x = fmaf(v.x, sc, sh);
        v.y = fmaf(v.y, sc, sh);
        v.z = fmaf(v.z, sc, sh);
        v.w = fmaf(v.w, sc, sh);
        ((float4*)out)[idx] = v;
    }
    if (out_size > NELEM) {
        for (int j = blockIdx.x * blockDim.x + threadIdx.x;
             j < out_size - NELEM && j < KK * VV * VV; j += stride)
            out[NELEM + j] = A[j];
    }
}

// ---------------- launch ----------------------------------------------------
extern "C" void kernel_launch(void* const* d_in, const int* in_sizes, int n_in,
                              void* d_out, int out_size) {
    const float* x     = (const float*)d_in[0];
    const float* A     = (const float*)d_in[1];
    const float* W     = (const float*)d_in[2];
    const float* b     = (const float*)d_in[3];
    const float* gamma = (const float*)d_in[4];
    const float* beta  = (const float*)d_in[5];
    float* out = (float*)d_out;

    cudaFuncSetAttribute(mgemm_kernel,
                         cudaFuncAttributeMaxDynamicSharedMemorySize, SMEM_M_TOTAL);

    prep_kernel<<<64, 256>>>(W, b, A);

    dim3 gz(TT / 10, NB);                      // (30, 64)
    zgemm_kernel<<<gz, 256>>>(x, A);

    dim3 gm(MBLK, NB);                         // (59, 64)
    mgemm_kernel<<<gm, 256, SMEM_M_TOTAL>>>(x, out);

    stats_kernel<<<CC, 256>>>(gamma, beta);

    normalize_kernel<<<2048, 256>>>(out, A, out_size);
}